// round 11
// baseline (speedup 1.0000x reference)
#include <cuda_runtime.h>
#include <cstdint>

#define DD 128
#define MAXN 50000
#define MAXE 600000

// Scratch (no cudaMalloc allowed): device globals.
__device__ float g_h1[MAXN * DD];
__device__ float g_h2[MAXN * DD];
__device__ float g_Bpre[3 * 8 * 4096];   // per layer: 8 chunks x 4096 floats (swizzled tf32 Wl||Wr)
__device__ int   g_cnt[MAXN];
__device__ int   g_off[MAXN + 1];
__device__ int   g_cur[MAXN];
__device__ int   g_srcl[MAXE];
__device__ int   g_part[64];
__device__ int   g_base[64];
__device__ int   g_is64;

__device__ __forceinline__ uint32_t sw128(uint32_t off) {
    return off ^ ((off >> 3) & 0x70);
}

__device__ __forceinline__ float to_tf32(float x) {
    float r;
    asm("cvt.rna.tf32.f32 %0, %1;" : "=f"(r) : "f"(x));
    return r;
}

// ===========================================================================
// dtype detection (int64 vs int32 edge_index)
// ===========================================================================
__global__ void detect_kernel(const unsigned int* __restrict__ ei, int nwords) {
    __shared__ unsigned int s_or;
    if (threadIdx.x == 0) s_or = 0u;
    __syncthreads();
    unsigned int v = 0u;
    int idx = 2 * (int)threadIdx.x + 1;
    if (idx < nwords) v = ei[idx];
    int idx2 = idx + 4096;
    if (idx2 < nwords) v |= ei[idx2];
    if (v) atomicOr(&s_or, v);
    __syncthreads();
    if (threadIdx.x == 0) g_is64 = (s_or == 0u) ? 1 : 0;
}

// ===========================================================================
// CSR build: histogram -> 3-phase multi-block scan -> atomic fill
// ===========================================================================
__global__ void hist_kernel(const void* __restrict__ eidx, int E) {
    int e0 = (blockIdx.x * blockDim.x + threadIdx.x) * 4;
    if (e0 >= E) return;
    int n = min(4, E - e0);
    int d[4];
    if (g_is64) {
        const long long* ei = (const long long*)eidx + E;
#pragma unroll
        for (int j = 0; j < 4; j++) if (j < n) d[j] = (int)ei[e0 + j];
    } else {
        const int* ei = (const int*)eidx + E;
#pragma unroll
        for (int j = 0; j < 4; j++) if (j < n) d[j] = ei[e0 + j];
    }
#pragma unroll
    for (int j = 0; j < 4; j++) if (j < n) atomicAdd(&g_cnt[d[j]], 1);
}

__global__ void scan1_kernel(int M) {
    __shared__ int red[32];
    int i = blockIdx.x * 1024 + threadIdx.x;
    int v = (i < M) ? g_cnt[i] : 0;
#pragma unroll
    for (int d = 16; d > 0; d >>= 1)
        v += __shfl_down_sync(0xffffffffu, v, d);
    if ((threadIdx.x & 31) == 0) red[threadIdx.x >> 5] = v;
    __syncthreads();
    if (threadIdx.x < 32) {
        int s = red[threadIdx.x];
#pragma unroll
        for (int d = 16; d > 0; d >>= 1)
            s += __shfl_down_sync(0xffffffffu, s, d);
        if (threadIdx.x == 0) g_part[blockIdx.x] = s;
    }
}

__global__ void scan2_kernel(int nblk, int M) {
    if (threadIdx.x == 0) {
        int run = 0;
        for (int b = 0; b < nblk; b++) {
            g_base[b] = run;
            run += g_part[b];
        }
        g_off[M] = run;
    }
}

__global__ void scan3_kernel(int M) {
    __shared__ int data[1024];
    int t = threadIdx.x;
    int i = blockIdx.x * 1024 + t;
    int v = (i < M) ? g_cnt[i] : 0;
    data[t] = v;
    __syncthreads();
#pragma unroll
    for (int d = 1; d < 1024; d <<= 1) {
        int o = (t >= d) ? data[t - d] : 0;
        __syncthreads();
        data[t] += o;
        __syncthreads();
    }
    if (i < M) {
        int excl = g_base[blockIdx.x] + data[t] - v;
        g_off[i] = excl;
        g_cur[i] = excl;
    }
}

__global__ void fill_kernel(const void* __restrict__ eidx, int E) {
    int e0 = (blockIdx.x * blockDim.x + threadIdx.x) * 4;
    if (e0 >= E) return;
    int n = min(4, E - e0);
    int s[4], d[4];
    if (g_is64) {
        const long long* ei = (const long long*)eidx;
#pragma unroll
        for (int j = 0; j < 4; j++)
            if (j < n) { s[j] = (int)ei[e0 + j]; d[j] = (int)ei[E + e0 + j]; }
    } else {
        const int* ei = (const int*)eidx;
#pragma unroll
        for (int j = 0; j < 4; j++)
            if (j < n) { s[j] = ei[e0 + j]; d[j] = ei[E + e0 + j]; }
    }
    int pos[4];
#pragma unroll
    for (int j = 0; j < 4; j++) if (j < n) pos[j] = atomicAdd(&g_cur[d[j]], 1);
#pragma unroll
    for (int j = 0; j < 4; j++) if (j < n) g_srcl[pos[j]] = s[j];
}

// ===========================================================================
// Weight pre-conversion (swizzled chunk-major tf32 image; see R6 notes)
// ===========================================================================
__global__ void prep_B(const float* __restrict__ Wl1, const float* __restrict__ Wr1,
                       const float* __restrict__ Wl2, const float* __restrict__ Wr2,
                       const float* __restrict__ Wl3, const float* __restrict__ Wr3) {
    int t = blockIdx.x * blockDim.x + threadIdx.x;   // 0..24575
    int layer = t >> 13;
    int rem = t & 8191;
    int chunk = rem >> 10;
    int fid = rem & 1023;
    const float* W;
    if (layer == 0) W = (chunk < 4) ? Wl1 : Wr1;
    else if (layer == 1) W = (chunk < 4) ? Wl2 : Wr2;
    else W = (chunk < 4) ? Wl3 : Wr3;
    int row = fid >> 3, c4 = fid & 7;
    float4 v = *(const float4*)(W + row * DD + (chunk & 3) * 32 + c4 * 4);
    v.x = to_tf32(v.x); v.y = to_tf32(v.y); v.z = to_tf32(v.z); v.w = to_tf32(v.w);
    uint32_t dst = (uint32_t)layer * 32768 + (uint32_t)chunk * 4096
                 + (sw128(row * 128 + c4 * 16) >> 2);
    *(float4*)(g_Bpre + dst) = v;
}

// ===========================================================================
// FUSED layer kernel: per 64-node CTA
//   1. stage X rows (chunks 4-7) + issue B chunk0 cp.async
//   2. gather neighbor means directly into A smem (chunks 0-3)
//   3. tf32 mma.sync mainloop (A fully smem-resident, B double-buffered)
//   Y = relu( mean @ Wl^T + bl + X @ Wr^T )
// SMEM: A = 8 chunks x 8KB (64 rows x 128B swizzled) = 64KB; B = 2 x 16KB.
// ===========================================================================
#define ACHK 8192
#define BOFF 65536
#define BCHK 16384
#define GEMM_SMEM (BOFF + 2 * BCHK)   // 98304

__device__ __forceinline__ uint32_t smem_u32(const void* p) {
    uint32_t a;
    asm("{ .reg .u64 t; cvta.to.shared.u64 t, %1; cvt.u32.u64 %0, t; }"
        : "=r"(a) : "l"(p));
    return a;
}

__device__ __forceinline__ void ldsm4(uint32_t* r, uint32_t addr) {
    asm volatile("ldmatrix.sync.aligned.m8n8.x4.shared.b16 {%0,%1,%2,%3}, [%4];"
                 : "=r"(r[0]), "=r"(r[1]), "=r"(r[2]), "=r"(r[3]) : "r"(addr));
}

__device__ __forceinline__ void mma_tf32(float* c, const uint32_t* a,
                                         const uint32_t* b) {
    asm("mma.sync.aligned.m16n8k8.row.col.f32.tf32.tf32.f32 "
        "{%0,%1,%2,%3}, {%4,%5,%6,%7}, {%8,%9}, {%0,%1,%2,%3};"
        : "+f"(c[0]), "+f"(c[1]), "+f"(c[2]), "+f"(c[3])
        : "r"(a[0]), "r"(a[1]), "r"(a[2]), "r"(a[3]), "r"(b[0]), "r"(b[1]));
}

__device__ __forceinline__ void cp16(uint32_t dst, const void* src) {
    asm volatile("cp.async.cg.shared.global [%0], [%1], 16;"
                 :: "r"(dst), "l"(src) : "memory");
}

__global__ void __launch_bounds__(128, 2)
layer_fused(const float* __restrict__ X, const float* __restrict__ Bpre,
            const float* __restrict__ bl, float* __restrict__ Y, int M)
{
    extern __shared__ char smem[];
    uint32_t sbase = smem_u32(smem);
    int tid = threadIdx.x;
    int lane = tid & 31;
    int wid = tid >> 5;
    int row0 = blockIdx.x << 6;

    // ---- issue B chunk 0 early ----
#pragma unroll
    for (int i = 0; i < 8; i++) {
        int fid = tid + i * 128;
        cp16(sbase + BOFF + (uint32_t)fid * 16, Bpre + fid * 4);
    }
    asm volatile("cp.async.commit_group;" ::: "memory");

    // ---- stage X rows into chunks 4-7 (64 rows x 128 floats) ----
#pragma unroll
    for (int i = 0; i < 16; i++) {
        int fid = tid + i * 128;          // 0..2047 float4
        int row = fid >> 5;               // 0..63
        int f4  = fid & 31;               // float4 col 0..31
        int chunk = 4 + (f4 >> 3);
        int c4 = f4 & 7;
        float4 v = make_float4(0.f, 0.f, 0.f, 0.f);
        int gr = row0 + row;
        if (gr < M) v = *(const float4*)(X + (size_t)gr * DD + f4 * 4);
        v.x = to_tf32(v.x); v.y = to_tf32(v.y);
        v.z = to_tf32(v.z); v.w = to_tf32(v.w);
        *(float4*)(smem + chunk * ACHK + sw128(row * 128 + c4 * 16)) = v;
    }

    // ---- gather means into chunks 0-3: warp w -> nodes w*16 .. w*16+15 ----
    {
        uint32_t adst = (uint32_t)(lane >> 3) * ACHK;       // chunk 0-3
        for (int ii = 0; ii < 16; ii++) {
            int rlocal = wid * 16 + ii;
            int node = row0 + rlocal;
            float4 v0 = make_float4(0.f, 0.f, 0.f, 0.f);
            float4 v1 = make_float4(0.f, 0.f, 0.f, 0.f);
            float4 v2 = make_float4(0.f, 0.f, 0.f, 0.f);
            float4 v3 = make_float4(0.f, 0.f, 0.f, 0.f);
            int s = 0, e = 0;
            if (node < M) { s = g_off[node]; e = g_off[node + 1]; }
            for (int base = s; base < e; base += 32) {
                int mysrc = (base + lane < e) ? g_srcl[base + lane] : 0;
                int n = min(32, e - base);
                int j = 0;
                for (; j + 3 < n; j += 4) {
                    int s0 = __shfl_sync(0xffffffffu, mysrc, j);
                    int s1 = __shfl_sync(0xffffffffu, mysrc, j + 1);
                    int s2 = __shfl_sync(0xffffffffu, mysrc, j + 2);
                    int s3 = __shfl_sync(0xffffffffu, mysrc, j + 3);
                    float4 t0 = *(const float4*)(X + (size_t)s0 * DD + lane * 4);
                    float4 t1 = *(const float4*)(X + (size_t)s1 * DD + lane * 4);
                    float4 t2 = *(const float4*)(X + (size_t)s2 * DD + lane * 4);
                    float4 t3 = *(const float4*)(X + (size_t)s3 * DD + lane * 4);
                    v0.x += t0.x; v0.y += t0.y; v0.z += t0.z; v0.w += t0.w;
                    v1.x += t1.x; v1.y += t1.y; v1.z += t1.z; v1.w += t1.w;
                    v2.x += t2.x; v2.y += t2.y; v2.z += t2.z; v2.w += t2.w;
                    v3.x += t3.x; v3.y += t3.y; v3.z += t3.z; v3.w += t3.w;
                }
                for (; j < n; j++) {
                    int s0 = __shfl_sync(0xffffffffu, mysrc, j);
                    float4 t0 = *(const float4*)(X + (size_t)s0 * DD + lane * 4);
                    v0.x += t0.x; v0.y += t0.y; v0.z += t0.z; v0.w += t0.w;
                }
            }
            float inv = 1.0f / fmaxf((float)(e - s), 1.0f);
            float4 o;
            o.x = to_tf32((v0.x + v1.x + v2.x + v3.x) * inv);
            o.y = to_tf32((v0.y + v1.y + v2.y + v3.y) * inv);
            o.z = to_tf32((v0.z + v1.z + v2.z + v3.z) * inv);
            o.w = to_tf32((v0.w + v1.w + v2.w + v3.w) * inv);
            *(float4*)(smem + adst + sw128(rlocal * 128 + (lane & 7) * 16)) = o;
        }
    }

    // ---- mma accumulators & lane geometry ----
    int warp_m = wid & 1;
    int warp_n = wid >> 1;
    float acc[2][8][4];
#pragma unroll
    for (int mi = 0; mi < 2; mi++)
#pragma unroll
        for (int ni = 0; ni < 8; ni++)
#pragma unroll
            for (int r = 0; r < 4; r++) acc[mi][ni][r] = 0.0f;

    int lane15 = lane & 15;
    uint32_t aseg = (lane >> 4) * 16;
    int arow = warp_m * 32 + lane15;
    uint32_t aswz = (arow & 7) * 16;
    uint32_t aoff = (uint32_t)arow * 128;

    uint32_t bseg = ((lane >> 3) & 1) * 16;
    int brow = warp_n * 64 + ((lane >> 4) * 8) + (lane & 7);
    uint32_t bswz = (brow & 7) * 16;
    uint32_t boff = (uint32_t)brow * 128;

    asm volatile("cp.async.wait_group 0;" ::: "memory");
    __syncthreads();

    // ---- mainloop: A resident, B double-buffered ----
#pragma unroll
    for (int kc = 0; kc < 8; kc++) {
        int cur = kc & 1;
        int nxt = cur ^ 1;
        const bool haven = (kc + 1) < 8;
        if (haven) {
            const float* bsrc = Bpre + (kc + 1) * 4096;
#pragma unroll
            for (int i = 0; i < 8; i++) {
                int fid = tid + i * 128;
                cp16(sbase + BOFF + (uint32_t)nxt * BCHK + (uint32_t)fid * 16,
                     bsrc + fid * 4);
            }
            asm volatile("cp.async.commit_group;" ::: "memory");
        }

        uint32_t aB = sbase + (uint32_t)kc * ACHK;
        uint32_t bB = sbase + BOFF + (uint32_t)cur * BCHK;
#pragma unroll
        for (int ks = 0; ks < 4; ks++) {
            uint32_t a[2][4], b[4][4];
            uint32_t ta = ((uint32_t)(ks * 32) + aseg) ^ aswz;
#pragma unroll
            for (int mi = 0; mi < 2; mi++)
                ldsm4(a[mi], aB + aoff + (uint32_t)mi * 2048 + ta);
            uint32_t tb = ((uint32_t)(ks * 32) + bseg) ^ bswz;
#pragma unroll
            for (int pi = 0; pi < 4; pi++)
                ldsm4(b[pi], bB + boff + (uint32_t)pi * 2048 + tb);
#pragma unroll
            for (int mi = 0; mi < 2; mi++)
#pragma unroll
                for (int pi = 0; pi < 4; pi++) {
                    mma_tf32(acc[mi][pi * 2 + 0], a[mi], &b[pi][0]);
                    mma_tf32(acc[mi][pi * 2 + 1], a[mi], &b[pi][2]);
                }
        }

        if (haven) {
            asm volatile("cp.async.wait_group 0;" ::: "memory");
            __syncthreads();
        }
    }

    // ---- epilogue ----
    int g = lane >> 2, t4 = lane & 3;
#pragma unroll
    for (int mi = 0; mi < 2; mi++) {
        int r_lo = row0 + warp_m * 32 + mi * 16 + g;
        int r_hi = r_lo + 8;
#pragma unroll
        for (int ni = 0; ni < 8; ni++) {
            int col = warp_n * 64 + ni * 8 + t4 * 2;
            float b0 = __ldg(bl + col), b1 = __ldg(bl + col + 1);
            if (r_lo < M) {
                float2 o;
                o.x = fmaxf(acc[mi][ni][0] + b0, 0.f);
                o.y = fmaxf(acc[mi][ni][1] + b1, 0.f);
                *(float2*)(Y + (size_t)r_lo * DD + col) = o;
            }
            if (r_hi < M) {
                float2 o;
                o.x = fmaxf(acc[mi][ni][2] + b0, 0.f);
                o.y = fmaxf(acc[mi][ni][3] + b1, 0.f);
                *(float2*)(Y + (size_t)r_hi * DD + col) = o;
            }
        }
    }
}

// ===========================================================================
// Launch
// ===========================================================================
extern "C" void kernel_launch(void* const* d_in, const int* in_sizes, int n_in,
                              void* d_out, int out_size) {
    const float* x  = (const float*)d_in[0];
    const void*  ei = d_in[1];
    const float* Wl1 = (const float*)d_in[2];
    const float* bl1 = (const float*)d_in[3];
    const float* Wr1 = (const float*)d_in[4];
    const float* Wl2 = (const float*)d_in[5];
    const float* bl2 = (const float*)d_in[6];
    const float* Wr2 = (const float*)d_in[7];
    const float* Wl3 = (const float*)d_in[8];
    const float* bl3 = (const float*)d_in[9];
    const float* Wr3 = (const float*)d_in[10];
    float* out = (float*)d_out;

    int M = in_sizes[0] / DD;
    int E = in_sizes[1] / 2;

    float *h1, *h2, *bpre;
    int *cnt;
    cudaGetSymbolAddress((void**)&h1,   g_h1);
    cudaGetSymbolAddress((void**)&h2,   g_h2);
    cudaGetSymbolAddress((void**)&bpre, g_Bpre);
    cudaGetSymbolAddress((void**)&cnt,  g_cnt);

    cudaFuncSetAttribute(layer_fused, cudaFuncAttributeMaxDynamicSharedMemorySize,
                         GEMM_SMEM);

    detect_kernel<<<1, 1024>>>((const unsigned int*)ei, 2 * E);
    prep_B<<<96, 256>>>(Wl1, Wr1, Wl2, Wr2, Wl3, Wr3);

    // CSR build (once per call; reused by all 3 layers)
    cudaMemsetAsync(cnt, 0, (size_t)M * sizeof(int));
    int e4_blocks = (E / 4 + 255) / 256 + 1;
    hist_kernel<<<e4_blocks, 256>>>(ei, E);
    int nblk = (M + 1023) / 1024;
    scan1_kernel<<<nblk, 1024>>>(M);
    scan2_kernel<<<1, 32>>>(nblk, M);
    scan3_kernel<<<nblk, 1024>>>(M);
    fill_kernel<<<e4_blocks, 256>>>(ei, E);

    int gm_blocks = (M + 63) / 64;

    const float* in = x;
    float* outs[3] = { h1, h2, out };
    const float* bls[3] = { bl1, bl2, bl3 };

    for (int L = 0; L < 3; L++) {
        layer_fused<<<gm_blocks, 128, GEMM_SMEM>>>(in, bpre + L * 32768,
                                                   bls[L], outs[L], M);
        in = outs[L];
    }
}

// round 12
// speedup vs baseline: 1.7569x; 1.7569x over previous
#include <cuda_runtime.h>
#include <cstdint>

#define DD 128
#define MAXN 50000
#define MAXE 600000

// Scratch (no cudaMalloc allowed): device globals.
__device__ float g_agg[MAXN * DD];
__device__ float g_h1[MAXN * DD];
__device__ float g_h2[MAXN * DD];
__device__ float g_Bpre[3 * 8 * 4096];   // per layer: 8 chunks x 4096 floats (swizzled tf32 Wl||Wr)
__device__ int   g_cnt[MAXN];
__device__ int   g_off[MAXN + 1];
__device__ int   g_cur[MAXN];
__device__ int   g_srcl[MAXE];
__device__ int   g_part[64];
__device__ int   g_base[64];
__device__ int   g_is64;

__device__ __forceinline__ uint32_t sw128(uint32_t off) {
    return off ^ ((off >> 3) & 0x70);
}

__device__ __forceinline__ float to_tf32(float x) {
    float r;
    asm("cvt.rna.tf32.f32 %0, %1;" : "=f"(r) : "f"(x));
    return r;
}

// ===========================================================================
// dtype detection (int64 vs int32 edge_index)
// ===========================================================================
__global__ void detect_kernel(const unsigned int* __restrict__ ei, int nwords) {
    __shared__ unsigned int s_or;
    if (threadIdx.x == 0) s_or = 0u;
    __syncthreads();
    unsigned int v = 0u;
    int idx = 2 * (int)threadIdx.x + 1;
    if (idx < nwords) v = ei[idx];
    int idx2 = idx + 4096;
    if (idx2 < nwords) v |= ei[idx2];
    if (v) atomicOr(&s_or, v);
    __syncthreads();
    if (threadIdx.x == 0) g_is64 = (s_or == 0u) ? 1 : 0;
}

// ===========================================================================
// CSR build: histogram -> 3-phase multi-block scan -> atomic fill
// 8 edges per thread for MLP (latency/atomic-bound, not BW-bound).
// ===========================================================================
__global__ void hist_kernel(const void* __restrict__ eidx, int E) {
    int e0 = (blockIdx.x * blockDim.x + threadIdx.x) * 8;
    if (e0 >= E) return;
    int n = min(8, E - e0);
    int d[8];
    if (g_is64) {
        const long long* ei = (const long long*)eidx + E;
#pragma unroll
        for (int j = 0; j < 8; j++) if (j < n) d[j] = (int)ei[e0 + j];
    } else {
        const int* ei = (const int*)eidx + E;
#pragma unroll
        for (int j = 0; j < 8; j++) if (j < n) d[j] = ei[e0 + j];
    }
#pragma unroll
    for (int j = 0; j < 8; j++) if (j < n) atomicAdd(&g_cnt[d[j]], 1);
}

// Phase 1: per-block sum of 1024 counts
__global__ void scan1_kernel(int M) {
    __shared__ int red[32];
    int i = blockIdx.x * 1024 + threadIdx.x;
    int v = (i < M) ? g_cnt[i] : 0;
#pragma unroll
    for (int d = 16; d > 0; d >>= 1)
        v += __shfl_down_sync(0xffffffffu, v, d);
    if ((threadIdx.x & 31) == 0) red[threadIdx.x >> 5] = v;
    __syncthreads();
    if (threadIdx.x < 32) {
        int s = red[threadIdx.x];
#pragma unroll
        for (int d = 16; d > 0; d >>= 1)
            s += __shfl_down_sync(0xffffffffu, s, d);
        if (threadIdx.x == 0) g_part[blockIdx.x] = s;
    }
}

// Phase 2: serial scan of block partials (<=64), write exclusive bases + total
__global__ void scan2_kernel(int nblk, int M) {
    if (threadIdx.x == 0) {
        int run = 0;
        for (int b = 0; b < nblk; b++) {
            g_base[b] = run;
            run += g_part[b];
        }
        g_off[M] = run;
    }
}

// Phase 3: Hillis-Steele inclusive scan within block + base, write off/cur
__global__ void scan3_kernel(int M) {
    __shared__ int data[1024];
    int t = threadIdx.x;
    int i = blockIdx.x * 1024 + t;
    int v = (i < M) ? g_cnt[i] : 0;
    data[t] = v;
    __syncthreads();
#pragma unroll
    for (int d = 1; d < 1024; d <<= 1) {
        int o = (t >= d) ? data[t - d] : 0;
        __syncthreads();
        data[t] += o;
        __syncthreads();
    }
    if (i < M) {
        int excl = g_base[blockIdx.x] + data[t] - v;
        g_off[i] = excl;
        g_cur[i] = excl;
    }
}

__global__ void fill_kernel(const void* __restrict__ eidx, int E) {
    int e0 = (blockIdx.x * blockDim.x + threadIdx.x) * 8;
    if (e0 >= E) return;
    int n = min(8, E - e0);
    int s[8], d[8];
    if (g_is64) {
        const long long* ei = (const long long*)eidx;
#pragma unroll
        for (int j = 0; j < 8; j++)
            if (j < n) { s[j] = (int)ei[e0 + j]; d[j] = (int)ei[E + e0 + j]; }
    } else {
        const int* ei = (const int*)eidx;
#pragma unroll
        for (int j = 0; j < 8; j++)
            if (j < n) { s[j] = ei[e0 + j]; d[j] = ei[E + e0 + j]; }
    }
    int pos[8];
#pragma unroll
    for (int j = 0; j < 8; j++) if (j < n) pos[j] = atomicAdd(&g_cur[d[j]], 1);
#pragma unroll
    for (int j = 0; j < 8; j++) if (j < n) g_srcl[pos[j]] = s[j];
}

// ===========================================================================
// Aggregation: one warp per node; gather neighbor rows, mean, store once.
// (At the LTS cap — do not touch.)
// ===========================================================================
__global__ void __launch_bounds__(256)
agg_kernel(const float* __restrict__ X, float* __restrict__ agg, int M) {
    int node = (int)((blockIdx.x * blockDim.x + threadIdx.x) >> 5);
    int lane = threadIdx.x & 31;
    if (node >= M) return;
    int s = g_off[node], e = g_off[node + 1];

    float4 v0 = make_float4(0.f, 0.f, 0.f, 0.f);
    float4 v1 = make_float4(0.f, 0.f, 0.f, 0.f);
    for (int base = s; base < e; base += 32) {
        int mysrc = (base + lane < e) ? g_srcl[base + lane] : 0;
        int n = min(32, e - base);
        int j = 0;
        for (; j + 1 < n; j += 2) {
            int s0 = __shfl_sync(0xffffffffu, mysrc, j);
            int s1 = __shfl_sync(0xffffffffu, mysrc, j + 1);
            float4 t0 = *(const float4*)(X + (size_t)s0 * DD + lane * 4);
            float4 t1 = *(const float4*)(X + (size_t)s1 * DD + lane * 4);
            v0.x += t0.x; v0.y += t0.y; v0.z += t0.z; v0.w += t0.w;
            v1.x += t1.x; v1.y += t1.y; v1.z += t1.z; v1.w += t1.w;
        }
        if (j < n) {
            int s0 = __shfl_sync(0xffffffffu, mysrc, j);
            float4 t0 = *(const float4*)(X + (size_t)s0 * DD + lane * 4);
            v0.x += t0.x; v0.y += t0.y; v0.z += t0.z; v0.w += t0.w;
        }
    }
    float inv = 1.0f / fmaxf((float)(e - s), 1.0f);
    float4 o;
    o.x = (v0.x + v1.x) * inv;
    o.y = (v0.y + v1.y) * inv;
    o.z = (v0.z + v1.z) * inv;
    o.w = (v0.w + v1.w) * inv;
    *(float4*)(agg + (size_t)node * DD + lane * 4) = o;
}

// ===========================================================================
// Weight pre-conversion (swizzled chunk-major tf32 image; see R6 notes)
// ===========================================================================
__global__ void prep_B(const float* __restrict__ Wl1, const float* __restrict__ Wr1,
                       const float* __restrict__ Wl2, const float* __restrict__ Wr2,
                       const float* __restrict__ Wl3, const float* __restrict__ Wr3) {
    int t = blockIdx.x * blockDim.x + threadIdx.x;   // 0..24575
    int layer = t >> 13;
    int rem = t & 8191;
    int chunk = rem >> 10;
    int fid = rem & 1023;
    const float* W;
    if (layer == 0) W = (chunk < 4) ? Wl1 : Wr1;
    else if (layer == 1) W = (chunk < 4) ? Wl2 : Wr2;
    else W = (chunk < 4) ? Wl3 : Wr3;
    int row = fid >> 3, c4 = fid & 7;
    float4 v = *(const float4*)(W + row * DD + (chunk & 3) * 32 + c4 * 4);
    v.x = to_tf32(v.x); v.y = to_tf32(v.y); v.z = to_tf32(v.z); v.w = to_tf32(v.w);
    uint32_t dst = (uint32_t)layer * 32768 + (uint32_t)chunk * 4096
                 + (sw128(row * 128 + c4 * 16) >> 2);
    *(float4*)(g_Bpre + dst) = v;
}

// ===========================================================================
// tf32 mma.sync fused GEMM with ldmatrix + cp.async(B) + reg-prefetch(A)
// CTA tile 64 rows x 128 cols, 128 threads, occ 4.
// ===========================================================================
#define ACHK 8192                 // A chunk: 64 rows x 128B
#define BCHK 16384                // B chunk: 128 rows x 128B
#define OFFB 16384                // after A0,A1
#define GEMM_SMEM (2 * ACHK + 2 * BCHK)   // 49152

__device__ __forceinline__ uint32_t smem_u32(const void* p) {
    uint32_t a;
    asm("{ .reg .u64 t; cvta.to.shared.u64 t, %1; cvt.u32.u64 %0, t; }"
        : "=r"(a) : "l"(p));
    return a;
}

__device__ __forceinline__ void ldsm4(uint32_t* r, uint32_t addr) {
    asm volatile("ldmatrix.sync.aligned.m8n8.x4.shared.b16 {%0,%1,%2,%3}, [%4];"
                 : "=r"(r[0]), "=r"(r[1]), "=r"(r[2]), "=r"(r[3]) : "r"(addr));
}

__device__ __forceinline__ void mma_tf32(float* c, const uint32_t* a,
                                         const uint32_t* b) {
    asm("mma.sync.aligned.m16n8k8.row.col.f32.tf32.tf32.f32 "
        "{%0,%1,%2,%3}, {%4,%5,%6,%7}, {%8,%9}, {%0,%1,%2,%3};"
        : "+f"(c[0]), "+f"(c[1]), "+f"(c[2]), "+f"(c[3])
        : "r"(a[0]), "r"(a[1]), "r"(a[2]), "r"(a[3]), "r"(b[0]), "r"(b[1]));
}

__device__ __forceinline__ void cp16(uint32_t dst, const void* src) {
    asm volatile("cp.async.cg.shared.global [%0], [%1], 16;"
                 :: "r"(dst), "l"(src) : "memory");
}

__global__ void __launch_bounds__(128, 4)
gemm_mma(const float* __restrict__ agg, const float* __restrict__ X,
         const float* __restrict__ Bpre, const float* __restrict__ bl,
         float* __restrict__ Y, int M)
{
    extern __shared__ char smem[];
    uint32_t sbase = smem_u32(smem);
    int tid = threadIdx.x;
    int lane = tid & 31;
    int wid = tid >> 5;
    int warp_m = wid & 1;     // row group of 32 (within 64)
    int warp_n = wid >> 1;    // col group of 64 (within 128)
    int row0 = blockIdx.x << 6;

    // A staging geometry: 64 rows x 32 floats = 512 float4 over 128 threads
    int st_row[4], st_c4[4];
    uint32_t st_sw[4];
#pragma unroll
    for (int i = 0; i < 4; i++) {
        int fid = tid + i * 128;       // 0..511
        st_row[i] = fid >> 3;          // 0..63
        st_c4[i]  = fid & 7;
        st_sw[i]  = sw128(st_row[i] * 128 + st_c4[i] * 16);
    }

    float acc[2][8][4];
#pragma unroll
    for (int mi = 0; mi < 2; mi++)
#pragma unroll
        for (int ni = 0; ni < 8; ni++)
#pragma unroll
            for (int r = 0; r < 4; r++) acc[mi][ni][r] = 0.0f;

    int lane15 = lane & 15;
    uint32_t aseg = (lane >> 4) * 16;
    int arow = warp_m * 32 + lane15;
    uint32_t aswz = (arow & 7) * 16;
    uint32_t aoff = (uint32_t)arow * 128;

    uint32_t bseg = ((lane >> 3) & 1) * 16;
    int brow = warp_n * 64 + ((lane >> 4) * 8) + (lane & 7);
    uint32_t bswz = (brow & 7) * 16;
    uint32_t boff = (uint32_t)brow * 128;

    // ---- prologue: chunk 0 ----
    {
#pragma unroll
        for (int i = 0; i < 8; i++) {
            int fid = tid + i * 128;   // 0..1023
            cp16(sbase + OFFB + (uint32_t)fid * 16, Bpre + fid * 4);
        }
        asm volatile("cp.async.commit_group;" ::: "memory");
#pragma unroll
        for (int i = 0; i < 4; i++) {
            int gr = row0 + st_row[i];
            float4 v = make_float4(0.f, 0.f, 0.f, 0.f);
            if (gr < M) v = *(const float4*)(agg + (size_t)gr * DD + st_c4[i] * 4);
            v.x = to_tf32(v.x); v.y = to_tf32(v.y);
            v.z = to_tf32(v.z); v.w = to_tf32(v.w);
            *(float4*)(smem + st_sw[i]) = v;
        }
        asm volatile("cp.async.wait_group 0;" ::: "memory");
        __syncthreads();
    }

#pragma unroll
    for (int kc = 0; kc < 8; kc++) {
        int cur = kc & 1;
        int nxt = cur ^ 1;
        float4 va[4];
        const bool haven = (kc + 1) < 8;
        if (haven) {
            const float* bsrc = Bpre + (kc + 1) * 4096;
#pragma unroll
            for (int i = 0; i < 8; i++) {
                int fid = tid + i * 128;
                cp16(sbase + OFFB + (uint32_t)nxt * BCHK + (uint32_t)fid * 16,
                     bsrc + fid * 4);
            }
            asm volatile("cp.async.commit_group;" ::: "memory");
            const float* An = ((kc + 1) < 4) ? agg : X;
            int klocal = ((kc + 1) & 3) * 32;
#pragma unroll
            for (int i = 0; i < 4; i++) {
                int gr = row0 + st_row[i];
                va[i] = make_float4(0.f, 0.f, 0.f, 0.f);
                if (gr < M)
                    va[i] = *(const float4*)(An + (size_t)gr * DD + klocal
                                             + st_c4[i] * 4);
            }
        }

        uint32_t aB = sbase + (uint32_t)cur * ACHK;
        uint32_t bB = sbase + OFFB + (uint32_t)cur * BCHK;
#pragma unroll
        for (int ks = 0; ks < 4; ks++) {
            uint32_t a[2][4], b[4][4];
            uint32_t ta = ((uint32_t)(ks * 32) + aseg) ^ aswz;
#pragma unroll
            for (int mi = 0; mi < 2; mi++)
                ldsm4(a[mi], aB + aoff + (uint32_t)mi * 2048 + ta);
            uint32_t tb = ((uint32_t)(ks * 32) + bseg) ^ bswz;
#pragma unroll
            for (int pi = 0; pi < 4; pi++)
                ldsm4(b[pi], bB + boff + (uint32_t)pi * 2048 + tb);
#pragma unroll
            for (int mi = 0; mi < 2; mi++)
#pragma unroll
                for (int pi = 0; pi < 4; pi++) {
                    mma_tf32(acc[mi][pi * 2 + 0], a[mi], &b[pi][0]);
                    mma_tf32(acc[mi][pi * 2 + 1], a[mi], &b[pi][2]);
                }
        }

        if (haven) {
#pragma unroll
            for (int i = 0; i < 4; i++) {
                float4 v = va[i];
                v.x = to_tf32(v.x); v.y = to_tf32(v.y);
                v.z = to_tf32(v.z); v.w = to_tf32(v.w);
                *(float4*)(smem + nxt * ACHK + st_sw[i]) = v;
            }
            asm volatile("cp.async.wait_group 0;" ::: "memory");
        }
        __syncthreads();
    }

    // ---- epilogue ----
    int g = lane >> 2, t4 = lane & 3;
#pragma unroll
    for (int mi = 0; mi < 2; mi++) {
        int r_lo = row0 + warp_m * 32 + mi * 16 + g;
        int r_hi = r_lo + 8;
#pragma unroll
        for (int ni = 0; ni < 8; ni++) {
            int col = warp_n * 64 + ni * 8 + t4 * 2;
            float b0 = __ldg(bl + col), b1 = __ldg(bl + col + 1);
            if (r_lo < M) {
                float2 o;
                o.x = fmaxf(acc[mi][ni][0] + b0, 0.f);
                o.y = fmaxf(acc[mi][ni][1] + b1, 0.f);
                *(float2*)(Y + (size_t)r_lo * DD + col) = o;
            }
            if (r_hi < M) {
                float2 o;
                o.x = fmaxf(acc[mi][ni][2] + b0, 0.f);
                o.y = fmaxf(acc[mi][ni][3] + b1, 0.f);
                *(float2*)(Y + (size_t)r_hi * DD + col) = o;
            }
        }
    }
}

// ===========================================================================
// Launch
// ===========================================================================
extern "C" void kernel_launch(void* const* d_in, const int* in_sizes, int n_in,
                              void* d_out, int out_size) {
    const float* x  = (const float*)d_in[0];
    const void*  ei = d_in[1];
    const float* Wl1 = (const float*)d_in[2];
    const float* bl1 = (const float*)d_in[3];
    const float* Wr1 = (const float*)d_in[4];
    const float* Wl2 = (const float*)d_in[5];
    const float* bl2 = (const float*)d_in[6];
    const float* Wr2 = (const float*)d_in[7];
    const float* Wl3 = (const float*)d_in[8];
    const float* bl3 = (const float*)d_in[9];
    const float* Wr3 = (const float*)d_in[10];
    float* out = (float*)d_out;

    int M = in_sizes[0] / DD;
    int E = in_sizes[1] / 2;

    float *agg, *h1, *h2, *bpre;
    int *cnt;
    cudaGetSymbolAddress((void**)&agg,  g_agg);
    cudaGetSymbolAddress((void**)&h1,   g_h1);
    cudaGetSymbolAddress((void**)&h2,   g_h2);
    cudaGetSymbolAddress((void**)&bpre, g_Bpre);
    cudaGetSymbolAddress((void**)&cnt,  g_cnt);

    cudaFuncSetAttribute(gemm_mma, cudaFuncAttributeMaxDynamicSharedMemorySize,
                         GEMM_SMEM);

    detect_kernel<<<1, 1024>>>((const unsigned int*)ei, 2 * E);
    prep_B<<<96, 256>>>(Wl1, Wr1, Wl2, Wr2, Wl3, Wr3);

    // CSR build (once per call; reused by all 3 layers)
    cudaMemsetAsync(cnt, 0, (size_t)M * sizeof(int));
    int e8_blocks = (E / 8 + 255) / 256 + 1;
    hist_kernel<<<e8_blocks, 256>>>(ei, E);
    int nblk = (M + 1023) / 1024;
    scan1_kernel<<<nblk, 1024>>>(M);
    scan2_kernel<<<1, 32>>>(nblk, M);
    scan3_kernel<<<nblk, 1024>>>(M);
    fill_kernel<<<e8_blocks, 256>>>(ei, E);

    int ag_blocks = (M * 32 + 255) / 256;
    int gm_blocks = (M + 63) / 64;

    const float* in = x;
    float* outs[3] = { h1, h2, out };
    const float* bls[3] = { bl1, bl2, bl3 };

    for (int L = 0; L < 3; L++) {
        agg_kernel<<<ag_blocks, 256>>>(in, agg, M);
        gemm_mma<<<gm_blocks, 128, GEMM_SMEM>>>(agg, in, bpre + L * 32768,
                                                bls[L], outs[L], M);
        in = outs[L];
    }
}